// round 11
// baseline (speedup 1.0000x reference)
#include <cuda_runtime.h>
#include <cuda_fp16.h>
#include <cstdint>

#define B_     4
#define DIM_   512
#define HW_    1024

// ---------------- scratch ----------------
__device__ float g_qm[64*DIM_];
__device__ float g_km[64*DIM_];
__device__ float g_qp[64*DIM_];
__device__ float g_kp[64*DIM_];
__device__ float g_attn[B_*8*16*16];
__device__ __half g_wv16[DIM_*DIM_];          // [d][k] fp16
__device__ __half g_vs[64ull*HW_*DIM_];       // [bt][p][k] fp16

__device__ __forceinline__ uint32_t smem_u32(const void* p) {
    uint32_t a;
    asm("{ .reg .u64 t; cvta.to.shared.u64 t, %1; cvt.u32.u64 %0, t; }" : "=r"(a) : "l"(p));
    return a;
}
__device__ __forceinline__ void ldm_x4(uint32_t* r, uint32_t addr) {
    asm volatile("ldmatrix.sync.aligned.m8n8.x4.shared.b16 {%0,%1,%2,%3}, [%4];"
                 : "=r"(r[0]), "=r"(r[1]), "=r"(r[2]), "=r"(r[3]) : "r"(addr));
}
__device__ __forceinline__ void mma_f16(float* c, const uint32_t* a, uint32_t b0, uint32_t b1) {
    asm volatile("mma.sync.aligned.m16n8k16.row.col.f32.f16.f16.f32 "
        "{%0,%1,%2,%3}, {%4,%5,%6,%7}, {%8,%9}, {%0,%1,%2,%3};"
        : "+f"(c[0]), "+f"(c[1]), "+f"(c[2]), "+f"(c[3])
        : "r"(a[0]), "r"(a[1]), "r"(a[2]), "r"(a[3]), "r"(b0), "r"(b1));
}
__device__ __forceinline__ void cpa16(uint32_t d, const void* s) {
    asm volatile("cp.async.cg.shared.global [%0], [%1], 16;"
                 :: "r"(d), "l"(__cvta_generic_to_global(s)));
}
#define CP_COMMIT() asm volatile("cp.async.commit_group;" ::: "memory")
#define CP_WAIT1()  asm volatile("cp.async.wait_group 1;" ::: "memory")

// ---------------- kernel 1: spatial means ----------------
__global__ void mean_kernel(const float* __restrict__ q, const float* __restrict__ k) {
    int w    = blockIdx.x * (blockDim.x >> 5) + (threadIdx.x >> 5);
    int lane = threadIdx.x & 31;
    const int NROW = 64*DIM_;
    const float* src; float* dst; int r;
    if (w < NROW) { src = q; dst = g_qm; r = w; }
    else          { src = k; dst = g_km; r = w - NROW; }
    const float4* p = (const float4*)(src + (size_t)r * HW_);
    float s = 0.f;
#pragma unroll
    for (int i = 0; i < 8; i++) { float4 v4 = p[lane + i*32]; s += v4.x + v4.y + v4.z + v4.w; }
#pragma unroll
    for (int m = 16; m; m >>= 1) s += __shfl_xor_sync(0xffffffffu, s, m);
    if (lane == 0) dst[r] = s * (1.f/1024.f);
}

// ---------------- kernel 2: pooled projections ----------------
__global__ void proj_kernel(const float* __restrict__ Wq, const float* __restrict__ Wk) {
    __shared__ float rowS[DIM_];
    __shared__ float Ws[DIM_*17];
    int rr  = blockIdx.x;
    int tid = threadIdx.x;
    const float* W; const float* in; float* out; float scale;
    if (rr < 64) { in = g_qm + rr*DIM_;      W = Wq; out = g_qp + rr*DIM_;      scale = 0.125f; }
    else         { in = g_km + (rr-64)*DIM_; W = Wk; out = g_kp + (rr-64)*DIM_; scale = 1.f;    }
    rowS[tid] = in[tid];
    float acc = 0.f;
    for (int e0 = 0; e0 < DIM_; e0 += 16) {
        __syncthreads();
#pragma unroll
        for (int i = 0; i < 16; i++) {
            int idx = tid + i*512;
            int d = idx >> 4, e = idx & 15;
            Ws[d*17 + e] = W[d*DIM_ + e0 + e];
        }
        __syncthreads();
#pragma unroll
        for (int e = 0; e < 16; e++) acc += rowS[e0 + e] * Ws[tid*17 + e];
    }
    out[tid] = acc * scale;
}

// ---------------- kernel 3: softmax ----------------
__global__ void attn_kernel() {
    int blk = blockIdx.x;
    int b = blk >> 7, h = (blk >> 4) & 7, s = blk & 15;
    int lane = threadIdx.x, t = lane & 15;
    const float* qr = g_qp + (size_t)(b*16 + s)*DIM_ + h*64;
    const float* kr = g_kp + (size_t)(b*16 + t)*DIM_ + h*64;
    float lg = 0.f;
#pragma unroll
    for (int j = 0; j < 64; j++) lg += qr[j] * kr[j];
    float mx = lg;
#pragma unroll
    for (int m = 8; m; m >>= 1) mx = fmaxf(mx, __shfl_xor_sync(0xffffffffu, mx, m));
    float e = __expf(lg - mx);
    float sm = e;
#pragma unroll
    for (int m = 8; m; m >>= 1) sm += __shfl_xor_sync(0xffffffffu, sm, m);
    if (lane < 16) g_attn[((b*8 + h)*16 + s)*16 + t] = e / sm;
}

// ---------------- kernel 4: Wv -> fp16 ----------------
__global__ void wvconv_kernel(const float* __restrict__ Wv) {
    int g = blockIdx.x * 512 + threadIdx.x;        // 0..32767
    const float* src = Wv + g*8;
    unsigned int w[4];
#pragma unroll
    for (int j = 0; j < 4; j++) {
        unsigned short u0 = __half_as_ushort(__float2half_rn(src[2*j]));
        unsigned short u1 = __half_as_ushort(__float2half_rn(src[2*j+1]));
        w[j] = ((unsigned)u1 << 16) | u0;
    }
    *(uint4*)(g_wv16 + (size_t)g*8) = make_uint4(w[0], w[1], w[2], w[3]);
}

// ---------------- kernel 5: v transpose + fp16 convert ----------------
__global__ __launch_bounds__(256) void convert_kernel(const float* __restrict__ v) {
    __shared__ float st[64*65];
    int pb = blockIdx.x, kb = blockIdx.y, bt = blockIdx.z;
#pragma unroll
    for (int i = 0; i < 4; i++) {
        int idx = threadIdx.x + i*256;
        int kk = idx >> 4, p4 = (idx & 15) * 4;
        float4 x = *(const float4*)(v + ((size_t)(bt*512 + kb*64 + kk))*HW_ + pb*64 + p4);
        st[kk*65 + p4 + 0] = x.x; st[kk*65 + p4 + 1] = x.y;
        st[kk*65 + p4 + 2] = x.z; st[kk*65 + p4 + 3] = x.w;
    }
    __syncthreads();
#pragma unroll
    for (int it = 0; it < 2; it++) {
        int task = threadIdx.x + it*256;
        int p = task >> 3, kg = task & 7;
        unsigned int w[4];
#pragma unroll
        for (int j = 0; j < 4; j++) {
            unsigned short u0 = __half_as_ushort(__float2half_rn(st[(kg*8 + 2*j    )*65 + p]));
            unsigned short u1 = __half_as_ushort(__float2half_rn(st[(kg*8 + 2*j + 1)*65 + p]));
            w[j] = ((unsigned)u1 << 16) | u0;
        }
        size_t e = ((size_t)(bt*HW_ + pb*64 + p))*512 + kb*64 + kg*8;
        *(uint4*)(g_vs + e) = make_uint4(w[0], w[1], w[2], w[3]);
    }
}

// ---------------- kernel 6: pipelined warp-mma GEMM (single-term fp16) + fused mix ----------------
// CTA: M=128 d x N=128 (16t x 8p) x K=512 in 8 chunks of 64.
// 3-stage cp.async, SINGLE sync per chunk: wait(1) -> sync -> issue c+2 -> mma c.
// Stage (32KB): A[128r x 128B] @0, B @16KB. Cs[128n][132] fp32 aliases stages.
#define STG 32768
#define DSMEM (3*STG)
extern __shared__ char dsm[];

__global__ __launch_bounds__(256, 2) void gemm_kernel(float* __restrict__ out) {
    __shared__ float s_attnT[512];
    int tid = threadIdx.x, lane = tid & 31, wid = tid >> 5;
    int md = blockIdx.x & 3;
    int px = blockIdx.x >> 2;
    int b  = blockIdx.y;
    int sh0 = (px & 7) * 4, sw0 = (px >> 3) * 2;
    int d0 = md * 128;

    uint32_t sb = smem_u32(dsm);

#pragma unroll
    for (int i = 0; i < 2; i++) {
        int idx = tid + i*256;
        int hl = idx >> 8, tt = (idx >> 4) & 15, ss = idx & 15;
        s_attnT[idx] = g_attn[((b*8 + md*2 + hl)*16 + ss)*16 + tt];
    }

    // A and B: 1024 16B-blocks per stage each -> 4 per thread
    int soff[4]; const __half* gA[4]; const __half* gB[4];
#pragma unroll
    for (int i = 0; i < 4; i++) {
        int idx = tid + i*256;              // 0..1023
        int r = idx >> 3, c = idx & 7;
        soff[i] = r*128 + (((c ^ (r & 7))) << 4);
        gA[i]   = g_wv16 + (size_t)(d0 + r)*512 + c*8;
        int t = r >> 3, pp = r & 7, ww = pp >> 2, hh = pp & 3;
        int pin = (sh0 + hh)*32 + (sw0 + ww);
        gB[i]   = g_vs + (size_t)((b*16 + t)*HW_ + pin)*512 + c*8;
    }

    int m0w = (wid & 3) * 32;
    int n0w = (wid >> 2) * 64;
    float acc[2][8][4];
#pragma unroll
    for (int mt = 0; mt < 2; mt++)
#pragma unroll
        for (int nt = 0; nt < 8; nt++)
#pragma unroll
            for (int j = 0; j < 4; j++) acc[mt][nt][j] = 0.f;

    // prologue: chunks 0,1 into stages 0,1
#pragma unroll
    for (int c = 0; c < 2; c++) {
        uint32_t sa = sb + c*STG;
#pragma unroll
        for (int i = 0; i < 4; i++) {
            cpa16(sa +         soff[i], gA[i] + c*64);
            cpa16(sa + 16384 + soff[i], gB[i] + c*64);
        }
        CP_COMMIT();
    }

#pragma unroll 1
    for (int c = 0; c < 8; c++) {
        CP_WAIT1();                           // chunk c arrived (c+1 may be in flight)
        __syncthreads();                      // all warps see stage c; stage (c+2)%3 free
        if (c + 2 < 8) {                      // prefetch c+2 BEFORE mma -> overlaps compute
            uint32_t sd = sb + ((c + 2) % 3)*STG;
#pragma unroll
            for (int i = 0; i < 4; i++) {
                cpa16(sd +         soff[i], gA[i] + (c+2)*64);
                cpa16(sd + 16384 + soff[i], gB[i] + (c+2)*64);
            }
        }
        CP_COMMIT();
        uint32_t sa  = sb + (c % 3)*STG;
        uint32_t sbb = sa + 16384;
#pragma unroll
        for (int ks = 0; ks < 4; ks++) {
            uint32_t ah[2][4];
            int arow_l = lane & 15;
            int ablk   = 2*ks + (lane >> 4);
#pragma unroll
            for (int mt = 0; mt < 2; mt++) {
                int row = m0w + mt*16 + arow_l;
                ldm_x4(ah[mt], sa + row*128 + ((ablk ^ (row & 7)) << 4));
            }
            int brow_l = (lane & 7) + ((lane & 16) ? 8 : 0);
            int bblk   = 2*ks + ((lane >> 3) & 1);
#pragma unroll
            for (int ntp = 0; ntp < 4; ntp++) {
                int row = n0w + ntp*16 + brow_l;
                uint32_t bh[4];
                ldm_x4(bh, sbb + row*128 + ((bblk ^ (row & 7)) << 4));
#pragma unroll
                for (int mt = 0; mt < 2; mt++) {
                    mma_f16(acc[mt][2*ntp  ], ah[mt], bh[0], bh[1]);
                    mma_f16(acc[mt][2*ntp+1], ah[mt], bh[2], bh[3]);
                }
            }
        }
    }
    __syncthreads();                          // all mma done; stages dead -> alias Cs

    // store accumulators: Cs[n][d], stride 132 (aliases stage buffers)
    float* Cs = (float*)dsm;
    int g = lane >> 2, tig = lane & 3;
#pragma unroll
    for (int mt = 0; mt < 2; mt++)
#pragma unroll
        for (int nt = 0; nt < 8; nt++) {
            int m = m0w + mt*16 + g;
            int n = n0w + nt*8 + 2*tig;
            Cs[n*132 + m]         = acc[mt][nt][0];
            Cs[(n+1)*132 + m]     = acc[mt][nt][1];
            Cs[n*132 + m + 8]     = acc[mt][nt][2];
            Cs[(n+1)*132 + m + 8] = acc[mt][nt][3];
        }
    __syncthreads();

    // mix epilogue
    {
        int d = tid & 127, ww = tid >> 7;
        int hl = d >> 6;
        const float* at = s_attnT + hl*256;
        unsigned long long ap[16][2];
#pragma unroll
        for (int s = 0; s < 16; s++) { ap[s][0] = 0ull; ap[s][1] = 0ull; }
#pragma unroll
        for (int t = 0; t < 16; t++) {
            float c0 = Cs[(t*8 + ww*4 + 0)*132 + d];
            float c1 = Cs[(t*8 + ww*4 + 1)*132 + d];
            float c2 = Cs[(t*8 + ww*4 + 2)*132 + d];
            float c3 = Cs[(t*8 + ww*4 + 3)*132 + d];
            unsigned long long cv01 = ((unsigned long long)__float_as_uint(c1) << 32) | __float_as_uint(c0);
            unsigned long long cv23 = ((unsigned long long)__float_as_uint(c3) << 32) | __float_as_uint(c2);
#pragma unroll
            for (int s = 0; s < 16; s++) {
                unsigned int wu = __float_as_uint(at[t*16 + s]);
                unsigned long long w2 = ((unsigned long long)wu << 32) | wu;
                asm("fma.rn.f32x2 %0, %1, %2, %0;" : "+l"(ap[s][0]) : "l"(cv01), "l"(w2));
                asm("fma.rn.f32x2 %0, %1, %2, %0;" : "+l"(ap[s][1]) : "l"(cv23), "l"(w2));
            }
        }
        float* op = out + ((size_t)(b*16)*512 + d0 + d)*HW_ + (sw0 + ww)*32 + sh0;
#pragma unroll
        for (int s = 0; s < 16; s++) {
            float4 v4;
            v4.x = __uint_as_float((unsigned int)(ap[s][0] & 0xffffffffull));
            v4.y = __uint_as_float((unsigned int)(ap[s][0] >> 32));
            v4.z = __uint_as_float((unsigned int)(ap[s][1] & 0xffffffffull));
            v4.w = __uint_as_float((unsigned int)(ap[s][1] >> 32));
            *(float4*)(op + (size_t)s*512*HW_) = v4;
        }
    }
}

// ---------------- launcher (single stream, no fork) ----------------
extern "C" void kernel_launch(void* const* d_in, const int* in_sizes, int n_in,
                              void* d_out, int out_size) {
    const float* q  = (const float*)d_in[0];
    const float* k  = (const float*)d_in[1];
    const float* v  = (const float*)d_in[2];
    const float* Wq = (const float*)d_in[3];
    const float* Wk = (const float*)d_in[4];
    const float* Wv = (const float*)d_in[5];
    float* out = (float*)d_out;

    cudaFuncSetAttribute(gemm_kernel, cudaFuncAttributeMaxDynamicSharedMemorySize, DSMEM);

    mean_kernel<<<8192, 256>>>(q, k);
    proj_kernel<<<128, 512>>>(Wq, Wk);
    attn_kernel<<<512, 32>>>();
    wvconv_kernel<<<64, 512>>>(Wv);
    dim3 gc(16, 8, 64);
    convert_kernel<<<gc, 256>>>(v);
    dim3 gg(512, 4);
    gemm_kernel<<<gg, 256, DSMEM>>>(out);
}

// round 12
// speedup vs baseline: 1.4081x; 1.4081x over previous
#include <cuda_runtime.h>
#include <cuda_fp16.h>
#include <cstdint>

#define B_     4
#define DIM_   512
#define HW_    1024

// ---------------- scratch ----------------
__device__ float g_qm[64*DIM_];
__device__ float g_km[64*DIM_];
__device__ float g_qp[64*DIM_];
__device__ float g_kp[64*DIM_];
__device__ float g_attn[B_*8*16*16];
__device__ __half g_wv16[DIM_*DIM_];          // [d][k] fp16
__device__ __half g_vs[64ull*HW_*DIM_];       // [bt][p][k] fp16

__device__ __forceinline__ uint32_t smem_u32(const void* p) {
    uint32_t a;
    asm("{ .reg .u64 t; cvta.to.shared.u64 t, %1; cvt.u32.u64 %0, t; }" : "=r"(a) : "l"(p));
    return a;
}
__device__ __forceinline__ void ldm_x4(uint32_t* r, uint32_t addr) {
    asm volatile("ldmatrix.sync.aligned.m8n8.x4.shared.b16 {%0,%1,%2,%3}, [%4];"
                 : "=r"(r[0]), "=r"(r[1]), "=r"(r[2]), "=r"(r[3]) : "r"(addr));
}
__device__ __forceinline__ void mma_f16(float* c, const uint32_t* a, uint32_t b0, uint32_t b1) {
    asm volatile("mma.sync.aligned.m16n8k16.row.col.f32.f16.f16.f32 "
        "{%0,%1,%2,%3}, {%4,%5,%6,%7}, {%8,%9}, {%0,%1,%2,%3};"
        : "+f"(c[0]), "+f"(c[1]), "+f"(c[2]), "+f"(c[3])
        : "r"(a[0]), "r"(a[1]), "r"(a[2]), "r"(a[3]), "r"(b0), "r"(b1));
}
__device__ __forceinline__ void cpa16(uint32_t d, const void* s) {
    asm volatile("cp.async.cg.shared.global [%0], [%1], 16;"
                 :: "r"(d), "l"(__cvta_generic_to_global(s)));
}
#define CP_COMMIT() asm volatile("cp.async.commit_group;" ::: "memory")
#define CP_WAIT2()  asm volatile("cp.async.wait_group 2;" ::: "memory")

// ---------------- kernel 1: spatial means ----------------
__global__ void mean_kernel(const float* __restrict__ q, const float* __restrict__ k) {
    int w    = blockIdx.x * (blockDim.x >> 5) + (threadIdx.x >> 5);
    int lane = threadIdx.x & 31;
    const int NROW = 64*DIM_;
    const float* src; float* dst; int r;
    if (w < NROW) { src = q; dst = g_qm; r = w; }
    else          { src = k; dst = g_km; r = w - NROW; }
    const float4* p = (const float4*)(src + (size_t)r * HW_);
    float s = 0.f;
#pragma unroll
    for (int i = 0; i < 8; i++) { float4 v4 = p[lane + i*32]; s += v4.x + v4.y + v4.z + v4.w; }
#pragma unroll
    for (int m = 16; m; m >>= 1) s += __shfl_xor_sync(0xffffffffu, s, m);
    if (lane == 0) dst[r] = s * (1.f/1024.f);
}

// ---------------- kernel 2: pooled projections ----------------
__global__ void proj_kernel(const float* __restrict__ Wq, const float* __restrict__ Wk) {
    __shared__ float rowS[DIM_];
    __shared__ float Ws[DIM_*17];
    int rr  = blockIdx.x;
    int tid = threadIdx.x;
    const float* W; const float* in; float* out; float scale;
    if (rr < 64) { in = g_qm + rr*DIM_;      W = Wq; out = g_qp + rr*DIM_;      scale = 0.125f; }
    else         { in = g_km + (rr-64)*DIM_; W = Wk; out = g_kp + (rr-64)*DIM_; scale = 1.f;    }
    rowS[tid] = in[tid];
    float acc = 0.f;
    for (int e0 = 0; e0 < DIM_; e0 += 16) {
        __syncthreads();
#pragma unroll
        for (int i = 0; i < 16; i++) {
            int idx = tid + i*512;
            int d = idx >> 4, e = idx & 15;
            Ws[d*17 + e] = W[d*DIM_ + e0 + e];
        }
        __syncthreads();
#pragma unroll
        for (int e = 0; e < 16; e++) acc += rowS[e0 + e] * Ws[tid*17 + e];
    }
    out[tid] = acc * scale;
}

// ---------------- kernel 3: softmax ----------------
__global__ void attn_kernel() {
    int blk = blockIdx.x;
    int b = blk >> 7, h = (blk >> 4) & 7, s = blk & 15;
    int lane = threadIdx.x, t = lane & 15;
    const float* qr = g_qp + (size_t)(b*16 + s)*DIM_ + h*64;
    const float* kr = g_kp + (size_t)(b*16 + t)*DIM_ + h*64;
    float lg = 0.f;
#pragma unroll
    for (int j = 0; j < 64; j++) lg += qr[j] * kr[j];
    float mx = lg;
#pragma unroll
    for (int m = 8; m; m >>= 1) mx = fmaxf(mx, __shfl_xor_sync(0xffffffffu, mx, m));
    float e = __expf(lg - mx);
    float sm = e;
#pragma unroll
    for (int m = 8; m; m >>= 1) sm += __shfl_xor_sync(0xffffffffu, sm, m);
    if (lane < 16) g_attn[((b*8 + h)*16 + s)*16 + t] = e / sm;
}

// ---------------- kernel 4: Wv -> fp16 ----------------
__global__ void wvconv_kernel(const float* __restrict__ Wv) {
    int g = blockIdx.x * 512 + threadIdx.x;        // 0..32767
    const float* src = Wv + g*8;
    unsigned int w[4];
#pragma unroll
    for (int j = 0; j < 4; j++) {
        unsigned short u0 = __half_as_ushort(__float2half_rn(src[2*j]));
        unsigned short u1 = __half_as_ushort(__float2half_rn(src[2*j+1]));
        w[j] = ((unsigned)u1 << 16) | u0;
    }
    *(uint4*)(g_wv16 + (size_t)g*8) = make_uint4(w[0], w[1], w[2], w[3]);
}

// ---------------- kernel 5: v transpose + fp16 convert ----------------
__global__ __launch_bounds__(256) void convert_kernel(const float* __restrict__ v) {
    __shared__ float st[64*65];
    int pb = blockIdx.x, kb = blockIdx.y, bt = blockIdx.z;
#pragma unroll
    for (int i = 0; i < 4; i++) {
        int idx = threadIdx.x + i*256;
        int kk = idx >> 4, p4 = (idx & 15) * 4;
        float4 x = *(const float4*)(v + ((size_t)(bt*512 + kb*64 + kk))*HW_ + pb*64 + p4);
        st[kk*65 + p4 + 0] = x.x; st[kk*65 + p4 + 1] = x.y;
        st[kk*65 + p4 + 2] = x.z; st[kk*65 + p4 + 3] = x.w;
    }
    __syncthreads();
#pragma unroll
    for (int it = 0; it < 2; it++) {
        int task = threadIdx.x + it*256;
        int p = task >> 3, kg = task & 7;
        unsigned int w[4];
#pragma unroll
        for (int j = 0; j < 4; j++) {
            unsigned short u0 = __half_as_ushort(__float2half_rn(st[(kg*8 + 2*j    )*65 + p]));
            unsigned short u1 = __half_as_ushort(__float2half_rn(st[(kg*8 + 2*j + 1)*65 + p]));
            w[j] = ((unsigned)u1 << 16) | u0;
        }
        size_t e = ((size_t)(bt*HW_ + pb*64 + p))*512 + kb*64 + kg*8;
        *(uint4*)(g_vs + e) = make_uint4(w[0], w[1], w[2], w[3]);
    }
}

// ---------------- kernel 6: pipelined warp-mma GEMM (single-term fp16) + fused mix ----------------
// CTA: M=128 d x N=128 (16t x 8p) x K=512 in 8 chunks of 64, 3-stage cp.async.
// R9 loop shape (empirical best): wait2 -> sync -> mma -> sync -> issue c+3.
// Stage (32KB): A[128r x 128B] @0, B[128r x 128B] @16KB. Cs[128n][132] fp32 aliases stages.
#define STG 32768
#define DSMEM (3*STG)
extern __shared__ char dsm[];

__global__ __launch_bounds__(256, 2) void gemm_kernel(float* __restrict__ out) {
    __shared__ float s_attnT[512];
    int tid = threadIdx.x, lane = tid & 31, wid = tid >> 5;
    int md = blockIdx.x & 3;
    int px = blockIdx.x >> 2;
    int b  = blockIdx.y;
    int sh0 = (px & 7) * 4, sw0 = (px >> 3) * 2;
    int d0 = md * 128;

    uint32_t sb = smem_u32(dsm);

#pragma unroll
    for (int i = 0; i < 2; i++) {
        int idx = tid + i*256;
        int hl = idx >> 8, tt = (idx >> 4) & 15, ss = idx & 15;
        s_attnT[idx] = g_attn[((b*8 + md*2 + hl)*16 + ss)*16 + tt];
    }

    // A and B: 1024 16B-blocks per stage each -> 4 per thread
    int soff[4]; const __half* gA[4]; const __half* gB[4];
#pragma unroll
    for (int i = 0; i < 4; i++) {
        int idx = tid + i*256;              // 0..1023
        int r = idx >> 3, c = idx & 7;
        soff[i] = r*128 + (((c ^ (r & 7))) << 4);
        gA[i]   = g_wv16 + (size_t)(d0 + r)*512 + c*8;
        int t = r >> 3, pp = r & 7, ww = pp >> 2, hh = pp & 3;
        int pin = (sh0 + hh)*32 + (sw0 + ww);
        gB[i]   = g_vs + (size_t)((b*16 + t)*HW_ + pin)*512 + c*8;
    }

    int m0w = (wid & 3) * 32;
    int n0w = (wid >> 2) * 64;
    float acc[2][8][4];
#pragma unroll
    for (int mt = 0; mt < 2; mt++)
#pragma unroll
        for (int nt = 0; nt < 8; nt++)
#pragma unroll
            for (int j = 0; j < 4; j++) acc[mt][nt][j] = 0.f;

    // prologue: chunks 0..2
#pragma unroll
    for (int c = 0; c < 3; c++) {
        uint32_t sa = sb + c*STG;
#pragma unroll
        for (int i = 0; i < 4; i++) {
            cpa16(sa +         soff[i], gA[i] + c*64);
            cpa16(sa + 16384 + soff[i], gB[i] + c*64);
        }
        CP_COMMIT();
    }

    int stg = 0;
#pragma unroll 1
    for (int c = 0; c < 8; c++) {
        CP_WAIT2();
        __syncthreads();
        uint32_t sa  = sb + stg*STG;
        uint32_t sbb = sa + 16384;
#pragma unroll
        for (int ks = 0; ks < 4; ks++) {
            uint32_t ah[2][4];
            int arow_l = lane & 15;
            int ablk   = 2*ks + (lane >> 4);
#pragma unroll
            for (int mt = 0; mt < 2; mt++) {
                int row = m0w + mt*16 + arow_l;
                ldm_x4(ah[mt], sa + row*128 + ((ablk ^ (row & 7)) << 4));
            }
            int brow_l = (lane & 7) + ((lane & 16) ? 8 : 0);
            int bblk   = 2*ks + ((lane >> 3) & 1);
#pragma unroll
            for (int ntp = 0; ntp < 4; ntp++) {
                int row = n0w + ntp*16 + brow_l;
                uint32_t bh[4];
                ldm_x4(bh, sbb + row*128 + ((bblk ^ (row & 7)) << 4));
#pragma unroll
                for (int mt = 0; mt < 2; mt++) {
                    mma_f16(acc[mt][2*ntp  ], ah[mt], bh[0], bh[1]);
                    mma_f16(acc[mt][2*ntp+1], ah[mt], bh[2], bh[3]);
                }
            }
        }
        __syncthreads();
        if (c + 3 < 8) {
            uint32_t sd = sb + stg*STG;
#pragma unroll
            for (int i = 0; i < 4; i++) {
                cpa16(sd +         soff[i], gA[i] + (c+3)*64);
                cpa16(sd + 16384 + soff[i], gB[i] + (c+3)*64);
            }
        }
        CP_COMMIT();
        stg = (stg + 1) == 3 ? 0 : stg + 1;
    }

    // store accumulators: Cs[n][d], stride 132 (aliases stage buffers)
    float* Cs = (float*)dsm;
    int g = lane >> 2, tig = lane & 3;
#pragma unroll
    for (int mt = 0; mt < 2; mt++)
#pragma unroll
        for (int nt = 0; nt < 8; nt++) {
            int m = m0w + mt*16 + g;
            int n = n0w + nt*8 + 2*tig;
            Cs[n*132 + m]         = acc[mt][nt][0];
            Cs[(n+1)*132 + m]     = acc[mt][nt][1];
            Cs[n*132 + m + 8]     = acc[mt][nt][2];
            Cs[(n+1)*132 + m + 8] = acc[mt][nt][3];
        }
    __syncthreads();

    // mix epilogue
    {
        int d = tid & 127, ww = tid >> 7;
        int hl = d >> 6;
        const float* at = s_attnT + hl*256;
        unsigned long long ap[16][2];
#pragma unroll
        for (int s = 0; s < 16; s++) { ap[s][0] = 0ull; ap[s][1] = 0ull; }
#pragma unroll
        for (int t = 0; t < 16; t++) {
            float c0 = Cs[(t*8 + ww*4 + 0)*132 + d];
            float c1 = Cs[(t*8 + ww*4 + 1)*132 + d];
            float c2 = Cs[(t*8 + ww*4 + 2)*132 + d];
            float c3 = Cs[(t*8 + ww*4 + 3)*132 + d];
            unsigned long long cv01 = ((unsigned long long)__float_as_uint(c1) << 32) | __float_as_uint(c0);
            unsigned long long cv23 = ((unsigned long long)__float_as_uint(c3) << 32) | __float_as_uint(c2);
#pragma unroll
            for (int s = 0; s < 16; s++) {
                unsigned int wu = __float_as_uint(at[t*16 + s]);
                unsigned long long w2 = ((unsigned long long)wu << 32) | wu;
                asm("fma.rn.f32x2 %0, %1, %2, %0;" : "+l"(ap[s][0]) : "l"(cv01), "l"(w2));
                asm("fma.rn.f32x2 %0, %1, %2, %0;" : "+l"(ap[s][1]) : "l"(cv23), "l"(w2));
            }
        }
        float* op = out + ((size_t)(b*16)*512 + d0 + d)*HW_ + (sw0 + ww)*32 + sh0;
#pragma unroll
        for (int s = 0; s < 16; s++) {
            float4 v4;
            v4.x = __uint_as_float((unsigned int)(ap[s][0] & 0xffffffffull));
            v4.y = __uint_as_float((unsigned int)(ap[s][0] >> 32));
            v4.z = __uint_as_float((unsigned int)(ap[s][1] & 0xffffffffull));
            v4.w = __uint_as_float((unsigned int)(ap[s][1] >> 32));
            *(float4*)(op + (size_t)s*512*HW_) = v4;
        }
    }
}

// ---------------- launcher (single stream) ----------------
extern "C" void kernel_launch(void* const* d_in, const int* in_sizes, int n_in,
                              void* d_out, int out_size) {
    const float* q  = (const float*)d_in[0];
    const float* k  = (const float*)d_in[1];
    const float* v  = (const float*)d_in[2];
    const float* Wq = (const float*)d_in[3];
    const float* Wk = (const float*)d_in[4];
    const float* Wv = (const float*)d_in[5];
    float* out = (float*)d_out;

    cudaFuncSetAttribute(gemm_kernel, cudaFuncAttributeMaxDynamicSharedMemorySize, DSMEM);

    mean_kernel<<<8192, 256>>>(q, k);
    proj_kernel<<<128, 512>>>(Wq, Wk);
    attn_kernel<<<512, 32>>>();
    wvconv_kernel<<<64, 512>>>(Wv);
    dim3 gc(16, 8, 64);
    convert_kernel<<<gc, 256>>>(v);
    dim3 gg(512, 4);
    gemm_kernel<<<gg, 256, DSMEM>>>(out);
}